// round 16
// baseline (speedup 1.0000x reference)
#include <cuda_runtime.h>
#include <cuda_fp16.h>
#include <cstdint>

// ---------------------------------------------------------------------------
// PriorNetwork round 16: 512-thread k_score, 2-tile pipelined iterations
// (NBUF=4, ONE barrier + one cp.async wait per 2 tiles, staging overlapped
// by a full body); fp16 mma.sync; in-place half2 epilogue + branch-skip
// rescue (EPS=4.0 hard bound); exact fp32 rescore; fused MLP QB=4.
// ---------------------------------------------------------------------------

#define D     64
#define H     512
#define QT    128
#define NT    128
#define CAP   4096
#define EPS   4.0f
#define NPAD  100480
#define BQ    2048
#define QB    4

#define BSTRIDE 40                       // words per tile row (16B-aligned)
#define BWORDS  (NT * BSTRIDE)           // 5120 words per buffer
#define NBUF    4
#define SM_WORDS (128 + NBUF * 64 + NBUF * BWORDS)   // 20864 words = 83456 B

__device__ unsigned long long g_best[BQ];
__device__ float    g_t2[NPAD];
__device__ uint32_t g_t2h[NPAD / 2];          // half2 packed t2 (col pairs)
__device__ uint32_t g_trh[(size_t)NPAD * 32]; // f16 train, pre-swizzled words
__device__ int      g_ccnt[BQ];
__device__ int      g_cand[BQ * CAP];

// ---- helpers --------------------------------------------------------------

__device__ __forceinline__ unsigned enc_f32(float f) {
    unsigned u = __float_as_uint(f);
    return (u & 0x80000000u) ? ~u : (u | 0x80000000u);
}
__device__ __forceinline__ float dec_f32(unsigned e) {
    unsigned u = (e & 0x80000000u) ? (e ^ 0x80000000u) : ~e;
    return __uint_as_float(u);
}
__device__ __forceinline__ uint32_t hfp(float lo, float hi) {   // {lo,hi} f16x2
    uint32_t r;
    asm("cvt.rn.f16x2.f32 %0, %1, %2;" : "=r"(r) : "f"(hi), "f"(lo));
    return r;
}
__device__ __forceinline__ void mma_f16(uint32_t& c0, uint32_t& c1,
                                        const uint32_t* a,
                                        uint32_t b0, uint32_t b1) {
    asm("mma.sync.aligned.m16n8k16.row.col.f16.f16.f16.f16 "
        "{%0,%1}, {%2,%3,%4,%5}, {%6,%7}, {%0,%1};"
        : "+r"(c0), "+r"(c1)
        : "r"(a[0]), "r"(a[1]), "r"(a[2]), "r"(a[3]), "r"(b0), "r"(b1));
}
__device__ __forceinline__ void cp16(uint32_t dst, const void* src) {
    asm volatile("cp.async.cg.shared.global [%0], [%1], 16;"
                 :: "r"(dst), "l"(src));
}
#define CP_COMMIT() asm volatile("cp.async.commit_group;")
#define CP_WAIT0()  asm volatile("cp.async.wait_group 0;")

// ---- k_prep: t2, t2h, pre-swizzled f16 train (chunked x3) -----------------
// word w at row n holds train[n][k0..k0+1], where wx = w ^ ((n&1)<<1),
//   ks = wx>>3, hh = wx&1, r4a = (wx&7)>>1, k0 = ks*16 + hh*8 + 2*r4a.

__global__ void k_prep(const float* __restrict__ train, int N, int B,
                       int base, int cnt) {
    int i = blockIdx.x * blockDim.x + threadIdx.x;
    if (base == 0 && i < B) g_ccnt[i] = 0;
    int n = base + i;
    if (i >= cnt || n >= NPAD) return;

    if (n < N) {
        const float* row = train + (size_t)n * D;
        float s = 0.f;
        for (int k = 0; k < D; k += 4) {
            float4 v = *(const float4*)&row[k];
            s += v.x * v.x + v.y * v.y + v.z * v.z + v.w * v.w;
        }
        g_t2[n] = s;
        ((__half*)g_t2h)[n] = __float2half_rn(s);
        const int px = (n & 1) << 1;
#pragma unroll
        for (int w = 0; w < 32; w++) {
            int wx  = w ^ px;
            int ks  = wx >> 3;
            int hh  = wx & 1;
            int r4a = (wx & 7) >> 1;
            int k0  = ks * 16 + hh * 8 + 2 * r4a;
            float2 p = *(const float2*)&row[k0];
            g_trh[(size_t)n * 32 + w] = hfp(p.x, p.y);
        }
    } else {
        g_t2[n] = 3.0e38f;
        ((__half*)g_t2h)[n] = __float2half_rn(3.0e38f);   // -> +inf
#pragma unroll
        for (int w = 0; w < 32; w++) g_trh[(size_t)n * 32 + w] = 0u;
    }
}

// ---- k_score (512 threads, 16 warps, m16 per warp, 2-tile iterations) -----

__device__ __forceinline__ void stage_tile(uint32_t bdst, uint32_t t2dst,
                                           int t, int tid) {
#pragma unroll
    for (int u = 0; u < 2; u++) {
        int c   = tid + u * 512;          // chunk 0..1023
        int n   = c >> 3;                 // row 0..127
        int off = (c & 7) * 4;            // word offset 0..28
        const char* src = (const char*)(g_trh + (size_t)(t * NT + n) * 32 + off);
        cp16(bdst + (uint32_t)(n * BSTRIDE + off) * 4u, src);
    }
    if (tid < 16)
        cp16(t2dst + tid * 16, (const char*)(g_t2h + t * 64 + tid * 4));
}

// Process one tile: MMA, in-place score, rescue; returns slot minima.
__device__ __forceinline__ void do_tile(
    const uint32_t* __restrict__ Bc, const uint32_t* __restrict__ t2c,
    int t, const uint32_t afr[4][4], const unsigned* __restrict__ cmin,
    int qbase, int qloc0, int qloc1, int wn, int g, int r4, int px,
    float& pm0, float& pm1) {

    const __half2 neg2 = __floats2half2_rn(-2.f, -2.f);

    uint32_t acc[8][2];
#pragma unroll
    for (int j = 0; j < 8; j++) { acc[j][0] = 0u; acc[j][1] = 0u; }

#pragma unroll
    for (int ks = 0; ks < 4; ks++) {
        uint2 b[8];
#pragma unroll
        for (int j = 0; j < 8; j++)
            b[j] = *(const uint2*)(Bc + (wn * 64 + j * 8 + g) * BSTRIDE +
                                   ((2 * r4) ^ px) + ks * 8);
#pragma unroll
        for (int j = 0; j < 8; j++)
            mma_f16(acc[j][0], acc[j][1], afr[ks], b[j].x, b[j].y);
    }

    // In-place scores: acc <- t2 - 2*acc.
#pragma unroll
    for (int j = 0; j < 8; j++) {
        __half2 t2p = *(const __half2*)&t2c[wn * 32 + j * 4 + r4];
        *(__half2*)&acc[j][0] = __hfma2(*(__half2*)&acc[j][0], neg2, t2p);
        *(__half2*)&acc[j][1] = __hfma2(*(__half2*)&acc[j][1], neg2, t2p);
    }

    // Slot minima + thresholds (own-tile min folded in: hard-bound safe).
    float mf[2], thr[2];
#pragma unroll
    for (int s = 0; s < 2; s++) {
        __half2 m = *(__half2*)&acc[0][s];
#pragma unroll
        for (int j = 1; j < 8; j++) m = __hmin2(m, *(__half2*)&acc[j][s]);
        mf[s] = __half2float(__hmin(__low2half(m), __high2half(m)));
    }
    thr[0] = fminf(dec_f32(cmin[qloc0]), mf[0]) + EPS;
    thr[1] = fminf(dec_f32(cmin[qloc1]), mf[1]) + EPS;

    if (mf[0] <= thr[0] || mf[1] <= thr[1]) {
        const int n0 = t * NT + wn * 64 + 2 * r4;
#pragma unroll
        for (int s = 0; s < 2; s++) {
            if (mf[s] > thr[s]) continue;
            const int q = qbase + (s ? qloc1 : qloc0);
#pragma unroll
            for (int j = 0; j < 8; j++) {
                __half2 sp = *(__half2*)&acc[j][s];
                float slo = __half2float(__low2half(sp));
                float shi = __half2float(__high2half(sp));
                if (slo <= thr[s]) {
                    int pos = atomicAdd(&g_ccnt[q], 1);
                    if (pos < CAP) g_cand[q * CAP + pos] = n0 + j * 8;
                }
                if (shi <= thr[s]) {
                    int pos = atomicAdd(&g_ccnt[q], 1);
                    if (pos < CAP) g_cand[q * CAP + pos] = n0 + j * 8 + 1;
                }
            }
        }
    }
    pm0 = fminf(pm0, mf[0]);
    pm1 = fminf(pm1, mf[1]);
}

__global__ void __launch_bounds__(512, 2)
k_score(const float* __restrict__ codes, int tiles_total, int tps) {
    extern __shared__ uint32_t smw[];
    unsigned* cmin  = (unsigned*)smw;                 // [128]
    uint32_t* t2hb  = smw + 128;                      // [NBUF][64]
    uint32_t* Bw    = smw + 128 + NBUF * 64;          // [NBUF][BWORDS]

    const uint32_t sb      = (uint32_t)__cvta_generic_to_shared(smw);
    const uint32_t t2base  = sb + 128u * 4u;
    const uint32_t bbase   = sb + (128u + NBUF * 64u) * 4u;

    const int tid  = threadIdx.x;
    const int lane = tid & 31;
    const int wid  = tid >> 5;        // 0..15
    const int wm   = wid >> 1;        // 0..7 : m16 strip
    const int wn   = wid & 1;         // 0..1 : n64 strip
    const int g    = lane >> 2;       // 0..7
    const int r4   = lane & 3;        // 0..3
    const int px   = (g & 1) << 1;
    const int qbase = blockIdx.x * QT;

    const int t0 = blockIdx.y * tps;
    const int t1 = min(t0 + tps, tiles_total);
    if (t0 >= t1) return;

    if (tid < QT) cmin[tid] = enc_f32(3.0e38f);

    // Prologue: async-stage tiles t0, t0+1 as ONE commit group.
    stage_tile(bbase, t2base, t0, tid);
    if (t0 + 1 < t1)
        stage_tile(bbase + BWORDS * 4u, t2base + 64u * 4u, t0 + 1, tid);
    CP_COMMIT();

    // A fragments (f16), m16 strip: afr[ks][4]  (overlaps the cp.asyncs)
    uint32_t afr[4][4];
    {
        const int qr = qbase + wm * 16 + g;
#pragma unroll
        for (int ks = 0; ks < 4; ks++) {
            const int k0 = ks * 16 + 2 * r4;
            float2 p0 = __ldg((const float2*)&codes[(size_t)qr * D + k0]);
            float2 p1 = __ldg((const float2*)&codes[(size_t)(qr + 8) * D + k0]);
            float2 p2 = __ldg((const float2*)&codes[(size_t)qr * D + k0 + 8]);
            float2 p3 = __ldg((const float2*)&codes[(size_t)(qr + 8) * D + k0 + 8]);
            afr[ks][0] = hfp(p0.x, p0.y);
            afr[ks][1] = hfp(p1.x, p1.y);
            afr[ks][2] = hfp(p2.x, p2.y);
            afr[ks][3] = hfp(p3.x, p3.y);
        }
    }

    const int qloc0 = wm * 16 + g;
    const int qloc1 = wm * 16 + g + 8;

    // 2-tile iterations. Invariants at loop top:
    //   - group in flight holds tiles T, T+1 (committed previous iter)
    //   - buffers of T+2, T+3 are free (their readers T-2, T-1 finished
    //     before the barrier below)
    for (int t = t0; t < t1; t += 2) {
        CP_WAIT0();          // tiles t, t+1 resident (this thread's copies)
        __syncthreads();     // ... and everyone else's; prior reads done

        // Stage the NEXT pair; consumed next iteration (full-body overlap).
        if (t + 2 < t1) {
            const int p2 = (t - t0 + 2) & 3;
            stage_tile(bbase + (uint32_t)p2 * BWORDS * 4u,
                       t2base + (uint32_t)p2 * 64u * 4u, t + 2, tid);
        }
        if (t + 3 < t1) {
            const int p3 = (t - t0 + 3) & 3;
            stage_tile(bbase + (uint32_t)p3 * BWORDS * 4u,
                       t2base + (uint32_t)p3 * 64u * 4u, t + 3, tid);
        }
        CP_COMMIT();         // uniform numbering (may be empty)

        float pm0 = 3.4e38f, pm1 = 3.4e38f;
        {
            const int p = (t - t0) & 3;
            do_tile(Bw + p * BWORDS, t2hb + p * 64, t, afr, cmin,
                    qbase, qloc0, qloc1, wn, g, r4, px, pm0, pm1);
        }
        if (t + 1 < t1) {
            const int p = (t - t0 + 1) & 3;
            do_tile(Bw + p * BWORDS, t2hb + p * 64, t + 1, afr, cmin,
                    qbase, qloc0, qloc1, wn, g, r4, px, pm0, pm1);
        }

        // Publish combined 2-tile minima to the shared running min.
        pm0 = fminf(pm0, __shfl_xor_sync(0xffffffffu, pm0, 1));
        pm0 = fminf(pm0, __shfl_xor_sync(0xffffffffu, pm0, 2));
        pm1 = fminf(pm1, __shfl_xor_sync(0xffffffffu, pm1, 1));
        pm1 = fminf(pm1, __shfl_xor_sync(0xffffffffu, pm1, 2));
        if (r4 == 0) {
            atomicMin(&cmin[qloc0], enc_f32(pm0));
            atomicMin(&cmin[qloc1], enc_f32(pm1));
        }
    }
}

// ---- exact fp32 rescore (one warp per query) ------------------------------

__global__ void __launch_bounds__(256)
k_rescore(const float* __restrict__ codes, const float* __restrict__ train,
          int B) {
    const int lane = threadIdx.x & 31;
    const int q = blockIdx.x * 8 + (threadIdx.x >> 5);
    if (q >= B) return;

    float4 qv[16];
#pragma unroll
    for (int i = 0; i < 16; i++)
        qv[i] = __ldg(&((const float4*)codes)[(size_t)q * 16 + i]);

    unsigned long long best = 0xFFFFFFFFFFFFFFFFULL;
    int cnt = min(g_ccnt[q], CAP);
    for (int i = lane; i < cnt; i += 32) {
        int n = g_cand[q * CAP + i];
        const float4* tr = (const float4*)(train + (size_t)n * D);
        float dot = 0.f;
#pragma unroll
        for (int k = 0; k < 16; k++) {
            float4 tv = __ldg(&tr[k]);
            dot = fmaf(qv[k].x, tv.x, dot);
            dot = fmaf(qv[k].y, tv.y, dot);
            dot = fmaf(qv[k].z, tv.z, dot);
            dot = fmaf(qv[k].w, tv.w, dot);
        }
        float s = fmaf(-2.f, dot, g_t2[n]);
        unsigned long long key =
            ((unsigned long long)enc_f32(s) << 32) | (unsigned)n;
        best = min(best, key);
    }
#pragma unroll
    for (int off = 16; off >= 1; off >>= 1)
        best = min(best, __shfl_xor_sync(0xffffffffu, best, off));
    if (lane == 0) g_best[q] = best;
}

// ---- fused MLP: 4 queries per CTA, stage-2 chain splitting ----------------

__global__ void __launch_bounds__(256)
k_mlp(const float* __restrict__ train,
      const float* __restrict__ W1, const float* __restrict__ b1,
      const float* __restrict__ Wu, const float* __restrict__ bu,
      const float* __restrict__ Ws, const float* __restrict__ bs,
      float* __restrict__ out, int B, int N) {
    __shared__ float x_s[QB][D];
    __shared__ float h_s[QB][H];
    const int qb  = blockIdx.x * QB;
    const int tid = threadIdx.x;

    if (tid < QB * (D / 4)) {
        int q  = tid >> 4;
        int c4 = tid & 15;
        unsigned ch = (unsigned)(g_best[qb + q] & 0xFFFFFFFFULL);
        ch = min(ch, (unsigned)(N - 1));    // crash guard; logic keeps it < N
        ((float4*)&x_s[q][0])[c4] =
            __ldg(&((const float4*)train)[(size_t)ch * (D / 4) + c4]);
    }
    __syncthreads();

    {   // h = relu(x @ W1 + b1): thread owns columns tid, tid+256
        float a0[QB], a1[QB];
#pragma unroll
        for (int q = 0; q < QB; q++) { a0[q] = 0.f; a1[q] = 0.f; }
        const int c0 = tid, c1 = tid + 256;
#pragma unroll 4
        for (int d = 0; d < D; d++) {
            float w0 = __ldg(&W1[d * H + c0]);
            float w1 = __ldg(&W1[d * H + c1]);
#pragma unroll
            for (int q = 0; q < QB; q++) {
                float x = x_s[q][d];
                a0[q] = fmaf(x, w0, a0[q]);
                a1[q] = fmaf(x, w1, a1[q]);
            }
        }
        float bb0 = __ldg(&b1[c0]), bb1 = __ldg(&b1[c1]);
#pragma unroll
        for (int q = 0; q < QB; q++) {
            h_s[q][c0] = fmaxf(a0[q] + bb0, 0.f);
            h_s[q][c1] = fmaxf(a1[q] + bb1, 0.f);
        }
    }
    __syncthreads();

    {   // mu / logstd: thread -> (d, which, 2-query half); 4-way chain split
        const int d     = tid & 63;
        const int which = (tid >> 6) & 1;
        const int qh    = tid >> 7;
        const float* W  = which ? Ws : Wu;
        const float* bb = which ? bs : bu;
        float a0[4] = {0.f, 0.f, 0.f, 0.f};
        float a1[4] = {0.f, 0.f, 0.f, 0.f};
        const float* h0 = h_s[qh * 2];
        const float* h1 = h_s[qh * 2 + 1];
#pragma unroll 2
        for (int h = 0; h < H; h += 4) {
#pragma unroll
            for (int u = 0; u < 4; u++) {
                float w = __ldg(&W[(size_t)(h + u) * D + d]);
                a0[u] = fmaf(h0[h + u], w, a0[u]);
                a1[u] = fmaf(h1[h + u], w, a1[u]);
            }
        }
        float bvv = __ldg(&bb[d]);
        float r0 = (a0[0] + a0[1]) + (a0[2] + a0[3]) + bvv;
        float r1 = (a1[0] + a1[1]) + (a1[2] + a1[3]) + bvv;
        out[(size_t)which * B * D + (size_t)(qb + qh * 2) * D + d]     = r0;
        out[(size_t)which * B * D + (size_t)(qb + qh * 2 + 1) * D + d] = r1;
    }
}

// ---- launch ---------------------------------------------------------------

extern "C" void kernel_launch(void* const* d_in, const int* in_sizes, int n_in,
                              void* d_out, int out_size) {
    const float* codes = (const float*)d_in[0];
    const float* train = (const float*)d_in[1];
    const float* W1    = (const float*)d_in[2];
    const float* b1    = (const float*)d_in[3];
    const float* Wu    = (const float*)d_in[4];
    const float* bu    = (const float*)d_in[5];
    const float* Ws    = (const float*)d_in[6];
    const float* bs    = (const float*)d_in[7];
    float* out = (float*)d_out;

    const int B = in_sizes[0] / D;   // 2048
    const int N = in_sizes[1] / D;   // 100000

    // 3 prep chunks (keeps k_score at the ncu capture slot).
    const int CH = 33536;            // 131 * 256
    k_prep<<<131, 256>>>(train, N, B, 0, CH);
    k_prep<<<131, 256>>>(train, N, B, CH, CH);
    k_prep<<<131, 256>>>(train, N, B, 2 * CH, NPAD - 2 * CH);

    const int tiles_total = (N + NT - 1) / NT;          // 782
    const int qtiles      = B / QT;                     // 16
    const int nsplits     = 18;                         // 288 CTAs = 2/SM wave
    const int tps         = (tiles_total + nsplits - 1) / nsplits;

    const size_t smem = (size_t)SM_WORDS * sizeof(uint32_t);   // 83456 B
    cudaFuncSetAttribute(k_score, cudaFuncAttributeMaxDynamicSharedMemorySize,
                         (int)smem);
    k_score<<<dim3(qtiles, nsplits), 512, smem>>>(codes, tiles_total, tps);

    k_rescore<<<(B + 7) / 8, 256>>>(codes, train, B);
    k_mlp<<<B / QB, 256>>>(train, W1, b1, Wu, bu, Ws, bs, out, B, N);
}